// round 1
// baseline (speedup 1.0000x reference)
#include <cuda_runtime.h>
#include <math.h>

// Problem constants (fixed by the reference):
//   x:  [B, T, C]  fp32, B=512, T=128, C=512
//   Wq/Wk/Wv: [H, C] fp32, H=64  (y = x @ W^T)
//   out: [B, T, H] fp32
#define TT 128
#define CC 512
#define HH 64
#define JJ 192          // 3*H fused projection width
#define KC 32           // K tile for projection GEMM

// smem pitches chosen for conflict-free access patterns
#define PX 129          // Xs pitch ([KC][T] transposed x tile)
#define PW 193          // Ws pitch ([KC][J] transposed W tile)
#define PQ 129          // Q/K/V pitch ([H][T])
#define PS 129          // S pitch   ([T][T])

#define OFF_XS 0
#define OFF_WS (OFF_XS + KC * PX)            // 4128
#define OFF_QS (OFF_WS + KC * PW)            // 10304
#define OFF_KS (OFF_QS + HH * PQ)            // 18560
#define OFF_VS (OFF_KS + HH * PQ)            // 26816
#define OFF_SS (OFF_VS + HH * PQ)            // 35072
#define SMEM_FLOATS (OFF_SS + TT * PS)       // 51584 floats = 206336 bytes

__global__ __launch_bounds__(256, 1)
void attn_fused_kernel(const float* __restrict__ x,
                       const float* __restrict__ Wq,
                       const float* __restrict__ Wk,
                       const float* __restrict__ Wv,
                       float* __restrict__ out)
{
    extern __shared__ float sm[];
    float* Xs = sm + OFF_XS;
    float* Ws = sm + OFF_WS;
    float* Qs = sm + OFF_QS;
    float* Ks = sm + OFF_KS;
    float* Vs = sm + OFF_VS;
    float* Ss = sm + OFF_SS;

    const int tid = threadIdx.x;
    const int tx  = tid & 15;   // 16 cols of thread grid
    const int ty  = tid >> 4;   // 16 rows of thread grid
    const int b   = blockIdx.x;
    const float* xb = x + (size_t)b * TT * CC;

    // ---------------- Phase 1: fused QKV projection ----------------
    // Y[t][j] = sum_c x[b][t][c] * W[j][c],  j in [0,192): Q|K|V
    // Thread tile: rows r = ty + 16*i (i<8), cols cc = tx + 16*j (j<12)
    float acc[8][12];
#pragma unroll
    for (int i = 0; i < 8; i++)
#pragma unroll
        for (int j = 0; j < 12; j++) acc[i][j] = 0.0f;

    for (int k0 = 0; k0 < CC; k0 += KC) {
        // Load x tile [128 t][32 c] transposed -> Xs[kc][t]  (conflict-free via PX=129)
#pragma unroll
        for (int q = 0; q < 4; q++) {
            int idx = q * 256 + tid;          // [0,1024): 128 rows * 8 float4
            int t  = idx >> 3;
            int c4 = idx & 7;
            float4 v = *reinterpret_cast<const float4*>(xb + t * CC + k0 + c4 * 4);
            Xs[(c4 * 4 + 0) * PX + t] = v.x;
            Xs[(c4 * 4 + 1) * PX + t] = v.y;
            Xs[(c4 * 4 + 2) * PX + t] = v.z;
            Xs[(c4 * 4 + 3) * PX + t] = v.w;
        }
        // Load W tile [192 j][32 c] transposed -> Ws[kc][j]
#pragma unroll
        for (int q = 0; q < 6; q++) {
            int idx = q * 256 + tid;          // [0,1536): 192 rows * 8 float4
            int j  = idx >> 3;
            int c4 = idx & 7;
            const float* Wsel = (j < 64) ? Wq : (j < 128) ? Wk : Wv;
            int jr = j & 63;
            float4 v = *reinterpret_cast<const float4*>(Wsel + jr * CC + k0 + c4 * 4);
            Ws[(c4 * 4 + 0) * PW + j] = v.x;
            Ws[(c4 * 4 + 1) * PW + j] = v.y;
            Ws[(c4 * 4 + 2) * PW + j] = v.z;
            Ws[(c4 * 4 + 3) * PW + j] = v.w;
        }
        __syncthreads();

#pragma unroll 4
        for (int kc = 0; kc < KC; kc++) {
            float a[8], bb[12];
#pragma unroll
            for (int i = 0; i < 8; i++)  a[i]  = Xs[kc * PX + ty + 16 * i];
#pragma unroll
            for (int j = 0; j < 12; j++) bb[j] = Ws[kc * PW + tx + 16 * j];
#pragma unroll
            for (int i = 0; i < 8; i++)
#pragma unroll
                for (int j = 0; j < 12; j++)
                    acc[i][j] = fmaf(a[i], bb[j], acc[i][j]);
        }
        __syncthreads();
    }

    // Scatter projection results to Q/K/V smem in [h][t] layout
#pragma unroll
    for (int j = 0; j < 12; j++) {
        int cc = tx + 16 * j;
        float* dst = (cc < 64) ? (Qs + cc * PQ)
                   : (cc < 128) ? (Ks + (cc - 64) * PQ)
                                : (Vs + (cc - 128) * PQ);
#pragma unroll
        for (int i = 0; i < 8; i++) dst[ty + 16 * i] = acc[i][j];
    }
    __syncthreads();

    // ---------------- Phase 2: S = (Q @ K^T) * scale, causal mask ----------------
    // Thread tile 8x8: rows r = ty+16i, cols s = tx+16j
    {
        float accS[8][8];
#pragma unroll
        for (int i = 0; i < 8; i++)
#pragma unroll
            for (int j = 0; j < 8; j++) accS[i][j] = 0.0f;

#pragma unroll 4
        for (int h = 0; h < HH; h++) {
            float a[8], bb[8];
#pragma unroll
            for (int i = 0; i < 8; i++) a[i]  = Qs[h * PQ + ty + 16 * i];
#pragma unroll
            for (int j = 0; j < 8; j++) bb[j] = Ks[h * PQ + tx + 16 * j];
#pragma unroll
            for (int i = 0; i < 8; i++)
#pragma unroll
                for (int j = 0; j < 8; j++)
                    accS[i][j] = fmaf(a[i], bb[j], accS[i][j]);
        }

        const float scale = 0.125f;  // 1/sqrt(64)
#pragma unroll
        for (int i = 0; i < 8; i++) {
            int r = ty + 16 * i;
#pragma unroll
            for (int j = 0; j < 8; j++) {
                int s2 = tx + 16 * j;
                Ss[r * PS + s2] = (s2 <= r) ? accS[i][j] * scale : -1e30f;
            }
        }
    }
    __syncthreads();

    // ---------------- Phase 3: row softmax (warp per 16 rows) ----------------
    {
        const int warp = tid >> 5;
        const int lane = tid & 31;
        for (int rr = 0; rr < 16; rr++) {
            int r = warp * 16 + rr;
            float v0 = Ss[r * PS + lane];
            float v1 = Ss[r * PS + lane + 32];
            float v2 = Ss[r * PS + lane + 64];
            float v3 = Ss[r * PS + lane + 96];
            float m = fmaxf(fmaxf(v0, v1), fmaxf(v2, v3));
#pragma unroll
            for (int o = 16; o > 0; o >>= 1)
                m = fmaxf(m, __shfl_xor_sync(0xffffffffu, m, o));
            float e0 = __expf(v0 - m);
            float e1 = __expf(v1 - m);
            float e2 = __expf(v2 - m);
            float e3 = __expf(v3 - m);
            float s = e0 + e1 + e2 + e3;
#pragma unroll
            for (int o = 16; o > 0; o >>= 1)
                s += __shfl_xor_sync(0xffffffffu, s, o);
            float inv = 1.0f / s;
            Ss[r * PS + lane]      = e0 * inv;
            Ss[r * PS + lane + 32] = e1 * inv;
            Ss[r * PS + lane + 64] = e2 * inv;
            Ss[r * PS + lane + 96] = e3 * inv;
        }
    }
    __syncthreads();

    // ---------------- Phase 4: O = P @ V ----------------
    // Thread tile 8x4: rows r = ty+16i, cols h = tx+16j  (64 cols total)
    {
        float accO[8][4];
#pragma unroll
        for (int i = 0; i < 8; i++)
#pragma unroll
            for (int j = 0; j < 4; j++) accO[i][j] = 0.0f;

#pragma unroll 4
        for (int s = 0; s < TT; s++) {
            float a[8], bb[4];
#pragma unroll
            for (int i = 0; i < 8; i++) a[i]  = Ss[(ty + 16 * i) * PS + s];
#pragma unroll
            for (int j = 0; j < 4; j++) bb[j] = Vs[(tx + 16 * j) * PQ + s];
#pragma unroll
            for (int i = 0; i < 8; i++)
#pragma unroll
                for (int j = 0; j < 4; j++)
                    accO[i][j] = fmaf(a[i], bb[j], accO[i][j]);
        }

#pragma unroll
        for (int i = 0; i < 8; i++) {
            int r = ty + 16 * i;
#pragma unroll
            for (int j = 0; j < 4; j++) {
                int h = tx + 16 * j;
                out[((size_t)b * TT + r) * HH + h] = accO[i][j];
            }
        }
    }
}

extern "C" void kernel_launch(void* const* d_in, const int* in_sizes, int n_in,
                              void* d_out, int out_size)
{
    const float* x  = (const float*)d_in[0];
    const float* Wq = (const float*)d_in[1];
    const float* Wk = (const float*)d_in[2];
    const float* Wv = (const float*)d_in[3];
    float* out = (float*)d_out;

    const int B = in_sizes[0] / (TT * CC);   // 512
    const size_t smem_bytes = (size_t)SMEM_FLOATS * sizeof(float);  // 206336

    cudaFuncSetAttribute(attn_fused_kernel,
                         cudaFuncAttributeMaxDynamicSharedMemorySize,
                         (int)smem_bytes);

    attn_fused_kernel<<<B, 256, smem_bytes>>>(x, Wq, Wk, Wv, out);
}

// round 3
// speedup vs baseline: 2.9953x; 2.9953x over previous
#include <cuda_runtime.h>
#include <cstdint>

// x [B=512, T=128, C=512] fp32; Wq/Wk/Wv [H=64, C=512]; out [B, T, 64] fp32.
// One CTA per batch, 8 warps. All GEMMs via mma.sync.m16n8k8 tf32 (HMMA path,
// available on base sm_100 target — tcgen05 is NOT, per round-2 ptxas errors).
#define TT 128
#define CC 512
#define HH 64
#define KT 64            // k-chunk for projection

// smem pitches (floats). pitch % 32 == 4 makes all fragment LDS patterns
// conflict-free: bank = (4*(lane>>2) + (lane&3)) % 32 is a lane permutation.
#define PA 68            // X tile [128][64], W tile [192][64]
#define PQ 68            // Q [128][64], K [128][64]
#define PV 132           // V^T [64][128]
#define PS 132           // S/P [128][128]

// smem float offsets
#define OFF_Q   0
#define OFF_K   (128 * PQ)                 // 8704
#define OFF_VT  (2 * 128 * PQ)             // 17408
#define OFF_SCR (OFF_VT + 64 * PV)         // 25856
#define OFF_X   OFF_SCR                    // scratch union: {X,W} then S
#define OFF_W   (OFF_SCR + 128 * PA)       // 34560
#define OFF_S   OFF_SCR
#define SMEM_FLOATS (OFF_W + 192 * PA)     // 47616 floats = 190464 bytes

__device__ __forceinline__ float tf32r(float f) {
    uint32_t u;
    asm("cvt.rna.tf32.f32 %0, %1;" : "=r"(u) : "f"(f));
    return __uint_as_float(u);
}
__device__ __forceinline__ uint32_t fb(float f) { return __float_as_uint(f); }

// D += A(16x8 row) * B(8x8 col), tf32 inputs, fp32 accum
__device__ __forceinline__ void mma8(float* d, const uint32_t* a, const uint32_t* b) {
    asm volatile(
        "mma.sync.aligned.m16n8k8.row.col.f32.tf32.tf32.f32 "
        "{%0,%1,%2,%3}, {%4,%5,%6,%7}, {%8,%9}, {%0,%1,%2,%3};"
        : "+f"(d[0]), "+f"(d[1]), "+f"(d[2]), "+f"(d[3])
        : "r"(a[0]), "r"(a[1]), "r"(a[2]), "r"(a[3]), "r"(b[0]), "r"(b[1]));
}

__global__ __launch_bounds__(256, 1)
void attn_hmma_kernel(const float* __restrict__ x,
                      const float* __restrict__ Wq,
                      const float* __restrict__ Wk,
                      const float* __restrict__ Wv,
                      float* __restrict__ out)
{
    extern __shared__ float sm[];
    float* Qs  = sm + OFF_Q;
    float* Ks  = sm + OFF_K;
    float* Vt  = sm + OFF_VT;
    float* Xs  = sm + OFF_X;
    float* Wsm = sm + OFF_W;
    float* Ss  = sm + OFF_S;

    const int tid  = threadIdx.x;
    const int wid  = tid >> 5;
    const int lane = tid & 31;
    const int l4   = lane >> 2;      // 0..7
    const int lk   = lane & 3;       // 0..3
    const int b    = blockIdx.x;
    const float* xb = x + (size_t)b * TT * CC;

    const int wr = wid >> 1;         // 0..3 : 32-row band
    const int wc = wid & 1;          // 0..1
    const int mb = wr * 32;

    // ================= Phase 1: Y[128,192] = x @ [Wq|Wk|Wv]^T =================
    float acc[2][12][4];
#pragma unroll
    for (int i = 0; i < 2; i++)
#pragma unroll
        for (int j = 0; j < 12; j++)
#pragma unroll
            for (int k = 0; k < 4; k++) acc[i][j][k] = 0.0f;

    const int nb1 = wc * 96;
#pragma unroll 1
    for (int ch = 0; ch < 8; ch++) {
        const int k0 = ch * KT;
        // X tile [128][64] -> Xs (tf32), 8 float4/thread
#pragma unroll
        for (int q = 0; q < 8; q++) {
            int idx = q * 256 + tid;
            int row = idx >> 4, c4 = idx & 15;
            float4 v = *reinterpret_cast<const float4*>(xb + row * CC + k0 + c4 * 4);
            float4 u = { tf32r(v.x), tf32r(v.y), tf32r(v.z), tf32r(v.w) };
            *reinterpret_cast<float4*>(Xs + row * PA + c4 * 4) = u;
        }
        // W tile [192][64] -> Wsm (tf32), 12 float4/thread
#pragma unroll
        for (int q = 0; q < 12; q++) {
            int idx = q * 256 + tid;
            int row = idx >> 4, c4 = idx & 15;
            const float* Wsel = (row < 64) ? Wq : (row < 128) ? Wk : Wv;
            int jr = row & 63;
            float4 v = *reinterpret_cast<const float4*>(Wsel + jr * CC + k0 + c4 * 4);
            float4 u = { tf32r(v.x), tf32r(v.y), tf32r(v.z), tf32r(v.w) };
            *reinterpret_cast<float4*>(Wsm + row * PA + c4 * 4) = u;
        }
        __syncthreads();

#pragma unroll
        for (int ks = 0; ks < 8; ks++) {
            const int kk = ks * 8;
            uint32_t a[2][4];
#pragma unroll
            for (int mt = 0; mt < 2; mt++) {
                const float* ap = Xs + (mb + mt * 16 + l4) * PA + kk + lk;
                a[mt][0] = fb(ap[0]);
                a[mt][1] = fb(ap[8 * PA]);
                a[mt][2] = fb(ap[4]);
                a[mt][3] = fb(ap[8 * PA + 4]);
            }
            uint32_t bf[12][2];
#pragma unroll
            for (int nt = 0; nt < 12; nt++) {
                const float* bp = Wsm + (nb1 + nt * 8 + l4) * PA + kk + lk;
                bf[nt][0] = fb(bp[0]);
                bf[nt][1] = fb(bp[4]);
            }
#pragma unroll
            for (int mt = 0; mt < 2; mt++)
#pragma unroll
                for (int nt = 0; nt < 12; nt++)
                    mma8(acc[mt][nt], a[mt], bf[nt]);
        }
        __syncthreads();
    }

    // Epilogue: route D frags to Qs / Ks / Vt (tf32 for next-stage operands)
#pragma unroll
    for (int mt = 0; mt < 2; mt++) {
        const int r0 = mb + mt * 16 + l4;
#pragma unroll
        for (int nt = 0; nt < 12; nt++) {
            const int c0 = nb1 + nt * 8 + 2 * lk;
            float d0 = tf32r(acc[mt][nt][0]), d1 = tf32r(acc[mt][nt][1]);
            float d2 = tf32r(acc[mt][nt][2]), d3 = tf32r(acc[mt][nt][3]);
            if (c0 < 64) {
                *reinterpret_cast<float2*>(Qs + r0 * PQ + c0)       = make_float2(d0, d1);
                *reinterpret_cast<float2*>(Qs + (r0 + 8) * PQ + c0) = make_float2(d2, d3);
            } else if (c0 < 128) {
                *reinterpret_cast<float2*>(Ks + r0 * PQ + (c0 - 64))       = make_float2(d0, d1);
                *reinterpret_cast<float2*>(Ks + (r0 + 8) * PQ + (c0 - 64)) = make_float2(d2, d3);
            } else {
                const int h = c0 - 128;
                Vt[h * PV + r0]           = d0;
                Vt[(h + 1) * PV + r0]     = d1;
                Vt[h * PV + r0 + 8]       = d2;
                Vt[(h + 1) * PV + r0 + 8] = d3;
            }
        }
    }
    __syncthreads();

    // ================= Phase 2: S = Q @ K^T (raw, fp32 accum) =================
    {
        const int nb2 = wc * 64;
        float accS[2][8][4];
#pragma unroll
        for (int i = 0; i < 2; i++)
#pragma unroll
            for (int j = 0; j < 8; j++)
#pragma unroll
                for (int k = 0; k < 4; k++) accS[i][j][k] = 0.0f;

#pragma unroll
        for (int ks = 0; ks < 8; ks++) {
            const int kk = ks * 8;
            uint32_t a[2][4];
#pragma unroll
            for (int mt = 0; mt < 2; mt++) {
                const float* ap = Qs + (mb + mt * 16 + l4) * PQ + kk + lk;
                a[mt][0] = fb(ap[0]);
                a[mt][1] = fb(ap[8 * PQ]);
                a[mt][2] = fb(ap[4]);
                a[mt][3] = fb(ap[8 * PQ + 4]);
            }
            uint32_t bf[8][2];
#pragma unroll
            for (int nt = 0; nt < 8; nt++) {
                const float* bp = Ks + (nb2 + nt * 8 + l4) * PQ + kk + lk;
                bf[nt][0] = fb(bp[0]);
                bf[nt][1] = fb(bp[4]);
            }
#pragma unroll
            for (int mt = 0; mt < 2; mt++)
#pragma unroll
                for (int nt = 0; nt < 8; nt++)
                    mma8(accS[mt][nt], a[mt], bf[nt]);
        }
#pragma unroll
        for (int mt = 0; mt < 2; mt++) {
            const int r0 = mb + mt * 16 + l4;
#pragma unroll
            for (int nt = 0; nt < 8; nt++) {
                const int c0 = nb2 + nt * 8 + 2 * lk;
                *reinterpret_cast<float2*>(Ss + r0 * PS + c0) =
                    make_float2(accS[mt][nt][0], accS[mt][nt][1]);
                *reinterpret_cast<float2*>(Ss + (r0 + 8) * PS + c0) =
                    make_float2(accS[mt][nt][2], accS[mt][nt][3]);
            }
        }
    }
    __syncthreads();

    // ================= Softmax (scale + causal mask), P stored tf32 =================
    {
        for (int rr = 0; rr < 16; rr++) {
            const int r = wid * 16 + rr;
            float v0 = Ss[r * PS + lane];
            float v1 = Ss[r * PS + lane + 32];
            float v2 = Ss[r * PS + lane + 64];
            float v3 = Ss[r * PS + lane + 96];
            v0 = (lane      <= r) ? v0 * 0.125f : -1e30f;
            v1 = (lane + 32 <= r) ? v1 * 0.125f : -1e30f;
            v2 = (lane + 64 <= r) ? v2 * 0.125f : -1e30f;
            v3 = (lane + 96 <= r) ? v3 * 0.125f : -1e30f;
            float m = fmaxf(fmaxf(v0, v1), fmaxf(v2, v3));
#pragma unroll
            for (int o = 16; o > 0; o >>= 1)
                m = fmaxf(m, __shfl_xor_sync(0xffffffffu, m, o));
            float e0 = __expf(v0 - m), e1 = __expf(v1 - m);
            float e2 = __expf(v2 - m), e3 = __expf(v3 - m);
            float s = e0 + e1 + e2 + e3;
#pragma unroll
            for (int o = 16; o > 0; o >>= 1)
                s += __shfl_xor_sync(0xffffffffu, s, o);
            const float inv = 1.0f / s;
            Ss[r * PS + lane]      = tf32r(e0 * inv);
            Ss[r * PS + lane + 32] = tf32r(e1 * inv);
            Ss[r * PS + lane + 64] = tf32r(e2 * inv);
            Ss[r * PS + lane + 96] = tf32r(e3 * inv);
        }
    }
    __syncthreads();

    // ================= Phase 3: O = P @ V =================
    {
        const int nb3 = wc * 32;
        float accO[2][4][4];
#pragma unroll
        for (int i = 0; i < 2; i++)
#pragma unroll
            for (int j = 0; j < 4; j++)
#pragma unroll
                for (int k = 0; k < 4; k++) accO[i][j][k] = 0.0f;

#pragma unroll
        for (int ks = 0; ks < 16; ks++) {
            const int kk = ks * 8;
            uint32_t a[2][4];
#pragma unroll
            for (int mt = 0; mt < 2; mt++) {
                const float* ap = Ss + (mb + mt * 16 + l4) * PS + kk + lk;
                a[mt][0] = fb(ap[0]);
                a[mt][1] = fb(ap[8 * PS]);
                a[mt][2] = fb(ap[4]);
                a[mt][3] = fb(ap[8 * PS + 4]);
            }
            uint32_t bf[4][2];
#pragma unroll
            for (int nt = 0; nt < 4; nt++) {
                const float* bp = Vt + (nb3 + nt * 8 + l4) * PV + kk + lk;
                bf[nt][0] = fb(bp[0]);
                bf[nt][1] = fb(bp[4]);
            }
#pragma unroll
            for (int mt = 0; mt < 2; mt++)
#pragma unroll
                for (int nt = 0; nt < 4; nt++)
                    mma8(accO[mt][nt], a[mt], bf[nt]);
        }

        // Direct global store (coalesced float2)
#pragma unroll
        for (int mt = 0; mt < 2; mt++) {
            const int r0 = mb + mt * 16 + l4;
#pragma unroll
            for (int nt = 0; nt < 4; nt++) {
                const int c0 = nb3 + nt * 8 + 2 * lk;
                *reinterpret_cast<float2*>(out + ((size_t)b * TT + r0) * HH + c0) =
                    make_float2(accO[mt][nt][0], accO[mt][nt][1]);
                *reinterpret_cast<float2*>(out + ((size_t)b * TT + r0 + 8) * HH + c0) =
                    make_float2(accO[mt][nt][2], accO[mt][nt][3]);
            }
        }
    }
}

extern "C" void kernel_launch(void* const* d_in, const int* in_sizes, int n_in,
                              void* d_out, int out_size)
{
    const float* x  = (const float*)d_in[0];
    const float* Wq = (const float*)d_in[1];
    const float* Wk = (const float*)d_in[2];
    const float* Wv = (const float*)d_in[3];
    float* out = (float*)d_out;

    const int B = in_sizes[0] / (TT * CC);                   // 512
    const size_t smem_bytes = (size_t)SMEM_FLOATS * sizeof(float);  // 190464

    cudaFuncSetAttribute(attn_hmma_kernel,
                         cudaFuncAttributeMaxDynamicSharedMemorySize,
                         (int)smem_bytes);
    attn_hmma_kernel<<<B, 256, smem_bytes>>>(x, Wq, Wk, Wv, out);
}